// round 6
// baseline (speedup 1.0000x reference)
#include <cuda_runtime.h>
#include <cstdint>
#include <math.h>

#define BB 2
#define NN 2048
#define CC 768
#define HH 12
#define HD 64
#define ROWS (BB*NN)          // 4096
#define C3 (3*CC)             // 2304
#define NSPLIT 2
#define KEYS_PER_SPLIT (NN/NSPLIT)   // 1024
#define QT (NN/128)                  // 16 q-tiles
#define NPART (BB*HH*QT*NSPLIT)      // 768

// Scratch (static device globals — no allocation)
__device__ float g_qkv[(size_t)ROWS * C3];   // [B*N, 3C] (tf32-rounded)
__device__ float g_att[(size_t)ROWS * CC];   // [B*N, C]  (tf32-rounded)
__device__ float g_xt [(size_t)ROWS * CC];   // tf32(x)
__device__ float g_wqt[(size_t)CC * C3];     // tf32(w_qkv)
__device__ float g_wpt[(size_t)CC * CC];     // tf32(w_proj)
__device__ float g_po [(size_t)NPART * 128 * HD];  // unnormalized partial O
__device__ float g_ml [(size_t)NPART * 128 * 2];   // per-row (m, l)

// ---------------------------------------------------------------------------
// helpers
// ---------------------------------------------------------------------------
__device__ __forceinline__ uint32_t smem_u32(const void* p) {
    uint32_t a;
    asm("{ .reg .u64 t; cvta.to.shared.u64 t, %1; cvt.u32.u64 %0, t; }"
        : "=r"(a) : "l"(p));
    return a;
}
__device__ __forceinline__ uint32_t f2tf32(float x) {
    uint32_t r;
    asm("cvt.rna.tf32.f32 %0, %1;" : "=r"(r) : "f"(x));
    return r;
}
__device__ __forceinline__ void cp16(uint32_t dst, const void* src) {
    asm volatile("cp.async.cg.shared.global [%0], [%1], 16;" :: "r"(dst), "l"(src));
}
__device__ __forceinline__ void cp_commit() {
    asm volatile("cp.async.commit_group;" ::: "memory");
}
template<int N> __device__ __forceinline__ void cp_wait() {
    asm volatile("cp.async.wait_group %0;" :: "n"(N) : "memory");
}
// D += A(16x8) * B(8x8), tf32 inputs (bit pattern in uint), fp32 accum
__device__ __forceinline__ void mma8(float* d, const uint32_t* a, const uint32_t* b) {
    asm volatile(
        "mma.sync.aligned.m16n8k8.row.col.f32.tf32.tf32.f32 "
        "{%0,%1,%2,%3}, {%4,%5,%6,%7}, {%8,%9}, {%0,%1,%2,%3};\n"
        : "+f"(d[0]), "+f"(d[1]), "+f"(d[2]), "+f"(d[3])
        : "r"(a[0]), "r"(a[1]), "r"(a[2]), "r"(a[3]), "r"(b[0]), "r"(b[1]));
}

// ---------------------------------------------------------------------------
// Pre-pass: round x, w_qkv, w_proj to tf32 (rna), stored as fp32 bits.
// ---------------------------------------------------------------------------
#define N1 ((ROWS*CC)/4)
#define N2 ((CC*C3)/4)
#define N3 ((CC*CC)/4)
__global__ void cvt_pass(const float* __restrict__ x,
                         const float* __restrict__ wq,
                         const float* __restrict__ wp)
{
    int idx = blockIdx.x * 256 + threadIdx.x;
    const float4* s; float4* d;
    if (idx < N1)                { s = (const float4*)x  + idx;       d = (float4*)g_xt  + idx; }
    else if (idx < N1 + N2)      { s = (const float4*)wq + (idx-N1);  d = (float4*)g_wqt + (idx-N1); }
    else if (idx < N1 + N2 + N3) { s = (const float4*)wp + (idx-N1-N2); d = (float4*)g_wpt + (idx-N1-N2); }
    else return;
    float4 v = *s;
    v.x = __uint_as_float(f2tf32(v.x));
    v.y = __uint_as_float(f2tf32(v.y));
    v.z = __uint_as_float(f2tf32(v.z));
    v.w = __uint_as_float(f2tf32(v.w));
    *d = v;
}

// ---------------------------------------------------------------------------
// tf32 warp-MMA GEMM, cp.async double-buffered.
// C[M,Nn] = A[M,K] @ W[K,Nn] (+bias). BM=128, BN=64, BK=32. 8 warps (4x2),
// warp tile 32x32. Inputs tf32-rounded. If CVT_OUT, output tf32-rounded.
// ---------------------------------------------------------------------------
#define APAD 36                 // (4*lr+lc)&31 distinct
#define BPAD 72                 // (8*lc+lr)&31 distinct
#define AWORDS (128*APAD)       // 4608
#define BWORDS (32*BPAD)        // 2304
#define BUFW   (AWORDS+BWORDS)  // 6912
#define GEMM_SMEM_BYTES (2*BUFW*4)   // 55296

template<bool HAS_BIAS, bool CVT_OUT>
__global__ __launch_bounds__(256) void gemm_cp(const float* __restrict__ A,
                                               const float* __restrict__ W,
                                               const float* __restrict__ bias,
                                               float* __restrict__ Cm,
                                               int M, int K, int Nn)
{
    extern __shared__ uint32_t smg[];
    const uint32_t sb = smem_u32(smg);
    const int tid  = threadIdx.x;
    const int wid  = tid >> 5;
    const int lane = tid & 31;
    const int wr   = wid & 3;
    const int wc   = wid >> 2;
    const int lr   = lane >> 2;
    const int lc   = lane & 3;
    const int row0 = blockIdx.y * 128;
    const int col0 = blockIdx.x * 64;

    float acc[2][4][4];
    #pragma unroll
    for (int i = 0; i < 2; i++)
        #pragma unroll
        for (int j = 0; j < 4; j++)
            #pragma unroll
            for (int v = 0; v < 4; v++) acc[i][j][v] = 0.f;

    const int ar  = tid >> 3,  ac4 = tid & 7;    // A: 128r x 8 f4, 4 iters
    const int bk  = tid >> 4,  bc4 = tid & 15;   // B: 32r x 16 f4, 2 iters

    #define ISSUE_TILE(ch, buf) do {                                              \
        const int _k0 = (ch) * 32;                                                \
        uint32_t _ab = sb + (buf) * (BUFW * 4);                                   \
        uint32_t _bb = _ab + AWORDS * 4;                                          \
        _Pragma("unroll")                                                         \
        for (int t = 0; t < 4; t++) {                                             \
            int r = ar + t * 32;                                                  \
            cp16(_ab + (r * APAD + ac4 * 4) * 4,                                  \
                 A + (size_t)(row0 + r) * K + _k0 + ac4 * 4);                     \
        }                                                                         \
        _Pragma("unroll")                                                         \
        for (int t = 0; t < 2; t++) {                                             \
            int k = bk + t * 16;                                                  \
            cp16(_bb + (k * BPAD + bc4 * 4) * 4,                                  \
                 W + (size_t)(_k0 + k) * Nn + col0 + bc4 * 4);                    \
        }                                                                         \
    } while (0)

    const int nch = K >> 5;
    ISSUE_TILE(0, 0); cp_commit();

    for (int ch = 0; ch < nch; ch++) {
        if (ch + 1 < nch) {
            ISSUE_TILE(ch + 1, (ch + 1) & 1); cp_commit();
            cp_wait<1>();
        } else {
            cp_wait<0>();
        }
        __syncthreads();

        const uint32_t* As = smg + (ch & 1) * BUFW;
        const uint32_t* Bs = As + AWORDS;

        #pragma unroll
        for (int kk = 0; kk < 4; kk++) {
            const int ks = kk * 8;
            uint32_t af[2][4];
            #pragma unroll
            for (int mt = 0; mt < 2; mt++) {
                int r = wr * 32 + mt * 16 + lr;
                af[mt][0] = As[r * APAD + ks + lc];
                af[mt][1] = As[(r + 8) * APAD + ks + lc];
                af[mt][2] = As[r * APAD + ks + lc + 4];
                af[mt][3] = As[(r + 8) * APAD + ks + lc + 4];
            }
            #pragma unroll
            for (int nt = 0; nt < 4; nt++) {
                int n = wc * 32 + nt * 8 + lr;
                uint32_t bf[2];
                bf[0] = Bs[(ks + lc) * BPAD + n];
                bf[1] = Bs[(ks + lc + 4) * BPAD + n];
                mma8(acc[0][nt], af[0], bf);
                mma8(acc[1][nt], af[1], bf);
            }
        }
        __syncthreads();
    }
    #undef ISSUE_TILE

    #pragma unroll
    for (int mt = 0; mt < 2; mt++) {
        int r = row0 + wr * 32 + mt * 16 + lr;
        #pragma unroll
        for (int nt = 0; nt < 4; nt++) {
            int c = col0 + wc * 32 + nt * 8 + 2 * lc;
            float2 v0 = make_float2(acc[mt][nt][0], acc[mt][nt][1]);
            float2 v1 = make_float2(acc[mt][nt][2], acc[mt][nt][3]);
            if (HAS_BIAS) {
                float2 bb = *(const float2*)(bias + c);
                v0.x += bb.x; v0.y += bb.y; v1.x += bb.x; v1.y += bb.y;
            }
            if (CVT_OUT) {
                v0.x = __uint_as_float(f2tf32(v0.x));
                v0.y = __uint_as_float(f2tf32(v0.y));
                v1.x = __uint_as_float(f2tf32(v1.x));
                v1.y = __uint_as_float(f2tf32(v1.y));
            }
            *(float2*)(Cm + (size_t)r * Nn + c) = v0;
            *(float2*)(Cm + (size_t)(r + 8) * Nn + c) = v1;
        }
    }
}

// ---------------------------------------------------------------------------
// Flash attention, split-K (2 splits of 1024 keys). 256 threads / 8 warps;
// each warp owns 16 query rows. Key tiles of 64, cp.async double-buffered.
// P re-fragmented via intra-quad shuffles (no smem round trip). Q fragments
// loaded directly from gmem. Partial (unnormalized o, m, l) to g_po/g_ml.
// smem: buf b: K[64][68] @ b*8960w, V[64][72] @ +4352w. Total 71.7KB.
// ---------------------------------------------------------------------------
#define KP 68
#define VP 72
#define KVBUFW (64*KP + 64*VP)           // 8960
#define ATTN_SMEM_BYTES (2*KVBUFW*4)     // 71680

__global__ __launch_bounds__(256) void attn_mma(const float* __restrict__ qkv,
                                                float* __restrict__ po,
                                                float* __restrict__ ml)
{
    extern __shared__ float sm[];
    uint32_t* smw = (uint32_t*)sm;
    const uint32_t sb = smem_u32(sm);
    const int tid  = threadIdx.x;
    const int wid  = tid >> 5;
    const int lane = tid & 31;
    const int lr   = lane >> 2;
    const int lc   = lane & 3;
    const int lc1  = lc & 1;
    const int i0   = (lane & ~3) | (lc >> 1);   // shfl src for a0/a1
    const int i2   = i0 + 2;                    // shfl src for a2/a3

    const int qt = blockIdx.x;
    const int bh = blockIdx.y;
    const int sp = blockIdx.z;
    const int b  = bh / HH;
    const int h  = bh % HH;
    const int q0 = qt * 128;
    const int k0 = sp * KEYS_PER_SPLIT;
    const int part = (bh * QT + qt) * NSPLIT + sp;
    const float* base = qkv + (size_t)b * NN * C3;

    const int kj  = tid >> 4, kc4 = tid & 15;    // KV loads: 16 rows/iter x 16 f4
    #define ISSUE_KV(kt, buf) do {                                                \
        uint32_t _kb = sb + (buf) * (KVBUFW * 4);                                 \
        uint32_t _vb = _kb + (64 * KP) * 4;                                       \
        _Pragma("unroll")                                                         \
        for (int t = 0; t < 4; t++) {                                             \
            int j = kj + t * 16;                                                  \
            const float* row = base + (size_t)((kt) + j) * C3 + h * HD + kc4 * 4; \
            cp16(_kb + (j * KP + kc4 * 4) * 4, row + CC);                         \
            cp16(_vb + (j * VP + kc4 * 4) * 4, row + 2 * CC);                     \
        }                                                                         \
    } while (0)

    ISSUE_KV(k0, 0); cp_commit();

    // Q fragments straight from gmem (rows tf32-rounded; *2^-3 exact)
    uint32_t qf[8][4];
    {
        const float scale = 0.125f;
        const float* qb = base + (size_t)(q0 + wid * 16) * C3 + h * HD;
        #pragma unroll
        for (int kk = 0; kk < 8; kk++) {
            qf[kk][0] = __float_as_uint(qb[(size_t)lr * C3 + kk * 8 + lc] * scale);
            qf[kk][1] = __float_as_uint(qb[(size_t)(lr + 8) * C3 + kk * 8 + lc] * scale);
            qf[kk][2] = __float_as_uint(qb[(size_t)lr * C3 + kk * 8 + lc + 4] * scale);
            qf[kk][3] = __float_as_uint(qb[(size_t)(lr + 8) * C3 + kk * 8 + lc + 4] * scale);
        }
    }

    float of[8][4];
    #pragma unroll
    for (int j = 0; j < 8; j++)
        #pragma unroll
        for (int v = 0; v < 4; v++) of[j][v] = 0.f;
    float m0 = -INFINITY, m1 = -INFINITY, l0 = 0.f, l1 = 0.f;

    const int ntile = KEYS_PER_SPLIT / 64;   // 16
    for (int it = 0; it < ntile; it++) {
        if (it + 1 < ntile) {
            ISSUE_KV(k0 + (it + 1) * 64, (it + 1) & 1); cp_commit();
            cp_wait<1>();
        } else {
            cp_wait<0>();
        }
        __syncthreads();

        const uint32_t* Ks = smw + (it & 1) * KVBUFW;
        const uint32_t* Vs = Ks + 64 * KP;

        // S = Q K^T
        float sf[8][4];
        #pragma unroll
        for (int nt = 0; nt < 8; nt++) {
            #pragma unroll
            for (int v = 0; v < 4; v++) sf[nt][v] = 0.f;
            #pragma unroll
            for (int kk = 0; kk < 8; kk++) {
                uint32_t bf[2];
                bf[0] = Ks[(nt * 8 + lr) * KP + kk * 8 + lc];
                bf[1] = Ks[(nt * 8 + lr) * KP + kk * 8 + lc + 4];
                mma8(sf[nt], qf[kk], bf);
            }
        }

        // online softmax
        float tm0 = -INFINITY, tm1 = -INFINITY;
        #pragma unroll
        for (int nt = 0; nt < 8; nt++) {
            tm0 = fmaxf(tm0, fmaxf(sf[nt][0], sf[nt][1]));
            tm1 = fmaxf(tm1, fmaxf(sf[nt][2], sf[nt][3]));
        }
        tm0 = fmaxf(tm0, __shfl_xor_sync(0xffffffff, tm0, 1));
        tm0 = fmaxf(tm0, __shfl_xor_sync(0xffffffff, tm0, 2));
        tm1 = fmaxf(tm1, __shfl_xor_sync(0xffffffff, tm1, 1));
        tm1 = fmaxf(tm1, __shfl_xor_sync(0xffffffff, tm1, 2));

        float mn0 = fmaxf(m0, tm0), mn1 = fmaxf(m1, tm1);
        float cr0 = __expf(m0 - mn0), cr1 = __expf(m1 - mn1);

        float rs0 = 0.f, rs1 = 0.f;
        #pragma unroll
        for (int nt = 0; nt < 8; nt++) {
            sf[nt][0] = __expf(sf[nt][0] - mn0);
            sf[nt][1] = __expf(sf[nt][1] - mn0);
            sf[nt][2] = __expf(sf[nt][2] - mn1);
            sf[nt][3] = __expf(sf[nt][3] - mn1);
            rs0 += sf[nt][0] + sf[nt][1];
            rs1 += sf[nt][2] + sf[nt][3];
        }
        rs0 += __shfl_xor_sync(0xffffffff, rs0, 1);
        rs0 += __shfl_xor_sync(0xffffffff, rs0, 2);
        rs1 += __shfl_xor_sync(0xffffffff, rs1, 1);
        rs1 += __shfl_xor_sync(0xffffffff, rs1, 2);
        l0 = l0 * cr0 + rs0;
        l1 = l1 * cr1 + rs1;
        m0 = mn0; m1 = mn1;

        #pragma unroll
        for (int dt = 0; dt < 8; dt++) {
            of[dt][0] *= cr0; of[dt][1] *= cr0;
            of[dt][2] *= cr1; of[dt][3] *= cr1;
        }

        // o += P V  — P A-fragments built via intra-quad shuffles:
        // C-frag (g,2t),(g,2t+1) -> A-frag (g,t): src lane (lane&~3)|(t>>1),
        // parity t&1; +2 lanes for cols t+4.
        #pragma unroll
        for (int kk = 0; kk < 8; kk++) {
            uint32_t pf[4];
            {
                float v00 = __shfl_sync(0xffffffff, sf[kk][0], i0);
                float v01 = __shfl_sync(0xffffffff, sf[kk][1], i0);
                pf[0] = f2tf32(lc1 ? v01 : v00);
                float v02 = __shfl_sync(0xffffffff, sf[kk][2], i0);
                float v03 = __shfl_sync(0xffffffff, sf[kk][3], i0);
                pf[1] = f2tf32(lc1 ? v03 : v02);
                float v20 = __shfl_sync(0xffffffff, sf[kk][0], i2);
                float v21 = __shfl_sync(0xffffffff, sf[kk][1], i2);
                pf[2] = f2tf32(lc1 ? v21 : v20);
                float v22 = __shfl_sync(0xffffffff, sf[kk][2], i2);
                float v23 = __shfl_sync(0xffffffff, sf[kk][3], i2);
                pf[3] = f2tf32(lc1 ? v23 : v22);
            }
            #pragma unroll
            for (int dt = 0; dt < 8; dt++) {
                uint32_t bf[2];
                bf[0] = Vs[(kk * 8 + lc) * VP + dt * 8 + lr];
                bf[1] = Vs[(kk * 8 + lc + 4) * VP + dt * 8 + lr];
                mma8(of[dt], pf, bf);
            }
        }
        __syncthreads();
    }
    #undef ISSUE_KV

    // write unnormalized partial o + (m,l)
    const int rl = wid * 16 + lr;
    float* pob = po + ((size_t)part * 128 + rl) * HD;
    #pragma unroll
    for (int dt = 0; dt < 8; dt++) {
        int c = dt * 8 + 2 * lc;
        *(float2*)(pob + c)          = make_float2(of[dt][0], of[dt][1]);
        *(float2*)(pob + 8 * HD + c) = make_float2(of[dt][2], of[dt][3]);
    }
    if (lc == 0) {
        *(float2*)(ml + ((size_t)part * 128 + rl) * 2)       = make_float2(m0, l0);
        *(float2*)(ml + ((size_t)part * 128 + rl + 8) * 2)   = make_float2(m1, l1);
    }
}

// ---------------------------------------------------------------------------
// Combine the 2 key-splits: o = sum_s e^{m_s-m} o_s / sum_s e^{m_s-m} l_s.
// grid (QT, B*H), 256 threads: 128 rows x 2 column-halves. tf32-rounds output.
// ---------------------------------------------------------------------------
__global__ __launch_bounds__(256) void attn_combine(const float* __restrict__ po,
                                                    const float* __restrict__ ml,
                                                    float* __restrict__ att)
{
    const int qt = blockIdx.x;
    const int bh = blockIdx.y;
    const int b  = bh / HH;
    const int h  = bh % HH;
    const int row  = threadIdx.x >> 1;
    const int half = threadIdx.x & 1;
    const int p0 = (bh * QT + qt) * NSPLIT;

    float2 ml0 = *(const float2*)(ml + ((size_t)p0 * 128 + row) * 2);
    float2 ml1 = *(const float2*)(ml + ((size_t)(p0 + 1) * 128 + row) * 2);
    float m = fmaxf(ml0.x, ml1.x);
    float w0 = __expf(ml0.x - m), w1 = __expf(ml1.x - m);
    float inv = 1.f / (w0 * ml0.y + w1 * ml1.y);
    w0 *= inv; w1 *= inv;

    const float* o0 = po + ((size_t)p0 * 128 + row) * HD + half * 32;
    const float* o1 = po + ((size_t)(p0 + 1) * 128 + row) * HD + half * 32;
    float* dst = att + ((size_t)(b * NN + qt * 128 + row)) * CC + h * HD + half * 32;
    #pragma unroll
    for (int c4 = 0; c4 < 8; c4++) {
        float4 a = *(const float4*)(o0 + c4 * 4);
        float4 d = *(const float4*)(o1 + c4 * 4);
        float4 v;
        v.x = __uint_as_float(f2tf32(w0 * a.x + w1 * d.x));
        v.y = __uint_as_float(f2tf32(w0 * a.y + w1 * d.y));
        v.z = __uint_as_float(f2tf32(w0 * a.z + w1 * d.z));
        v.w = __uint_as_float(f2tf32(w0 * a.w + w1 * d.w));
        *(float4*)(dst + c4 * 4) = v;
    }
}

// ---------------------------------------------------------------------------
extern "C" void kernel_launch(void* const* d_in, const int* in_sizes, int n_in,
                              void* d_out, int out_size)
{
    const float* x      = (const float*)d_in[0];
    const float* w_qkv  = (const float*)d_in[1];
    const float* w_proj = (const float*)d_in[2];
    const float* b_proj = (const float*)d_in[3];
    float* out = (float*)d_out;

    float *qkv, *att, *xt, *wqt, *wpt, *po, *ml;
    cudaGetSymbolAddress((void**)&qkv, g_qkv);
    cudaGetSymbolAddress((void**)&att, g_att);
    cudaGetSymbolAddress((void**)&xt,  g_xt);
    cudaGetSymbolAddress((void**)&wqt, g_wqt);
    cudaGetSymbolAddress((void**)&wpt, g_wpt);
    cudaGetSymbolAddress((void**)&po,  g_po);
    cudaGetSymbolAddress((void**)&ml,  g_ml);

    static bool attr_done = false;
    if (!attr_done) {
        cudaFuncSetAttribute(attn_mma, cudaFuncAttributeMaxDynamicSharedMemorySize,
                             ATTN_SMEM_BYTES);
        cudaFuncSetAttribute(gemm_cp<false, true>,
                             cudaFuncAttributeMaxDynamicSharedMemorySize, GEMM_SMEM_BYTES);
        cudaFuncSetAttribute(gemm_cp<true, false>,
                             cudaFuncAttributeMaxDynamicSharedMemorySize, GEMM_SMEM_BYTES);
        attr_done = true;
    }

    // 0) tf32 pre-round
    {
        int total = N1 + N2 + N3;
        cvt_pass<<<(total + 255) / 256, 256>>>(x, w_qkv, w_proj);
    }
    // 1) QKV projection (tf32 out)
    {
        dim3 grid(C3 / 64, ROWS / 128);
        gemm_cp<false, true><<<grid, 256, GEMM_SMEM_BYTES>>>(xt, wqt, nullptr, qkv,
                                                             ROWS, CC, C3);
    }
    // 2) attention partials (split-K over keys)
    {
        dim3 grid(QT, BB * HH, NSPLIT);
        attn_mma<<<grid, 256, ATTN_SMEM_BYTES>>>(qkv, po, ml);
    }
    // 2b) combine splits (tf32 out)
    {
        dim3 grid(QT, BB * HH);
        attn_combine<<<grid, 256>>>(po, ml, att);
    }
    // 3) output projection + bias (fp32 out)
    {
        dim3 grid(CC / 64, ROWS / 128);
        gemm_cp<true, false><<<grid, 256, GEMM_SMEM_BYTES>>>(att, wpt, b_proj, out,
                                                             ROWS, CC, CC);
    }
}

// round 7
// speedup vs baseline: 1.1035x; 1.1035x over previous
#include <cuda_runtime.h>
#include <cstdint>
#include <math.h>

#define BB 2
#define NN 2048
#define CC 768
#define HH 12
#define HD 64
#define ROWS (BB*NN)          // 4096
#define C3 (3*CC)             // 2304
#define QT (NN/128)           // 16 q-tiles

// Scratch (static device globals — no allocation)
__device__ float g_qkv[(size_t)ROWS * C3];   // [B*N, 3C] (tf32-rounded)
__device__ float g_att[(size_t)ROWS * CC];   // [B*N, C]  (tf32-rounded)
__device__ float g_xt [(size_t)ROWS * CC];   // tf32(x)
__device__ float g_wqt[(size_t)CC * C3];     // tf32(w_qkv)
__device__ float g_wpt[(size_t)CC * CC];     // tf32(w_proj)

// ---------------------------------------------------------------------------
// helpers
// ---------------------------------------------------------------------------
__device__ __forceinline__ uint32_t smem_u32(const void* p) {
    uint32_t a;
    asm("{ .reg .u64 t; cvta.to.shared.u64 t, %1; cvt.u32.u64 %0, t; }"
        : "=r"(a) : "l"(p));
    return a;
}
__device__ __forceinline__ uint32_t f2tf32(float x) {
    uint32_t r;
    asm("cvt.rna.tf32.f32 %0, %1;" : "=r"(r) : "f"(x));
    return r;
}
__device__ __forceinline__ void cp16(uint32_t dst, const void* src) {
    asm volatile("cp.async.cg.shared.global [%0], [%1], 16;" :: "r"(dst), "l"(src));
}
__device__ __forceinline__ void cp_commit() {
    asm volatile("cp.async.commit_group;" ::: "memory");
}
template<int N> __device__ __forceinline__ void cp_wait() {
    asm volatile("cp.async.wait_group %0;" :: "n"(N) : "memory");
}
// D += A(16x8) * B(8x8), tf32 inputs (bit pattern in uint), fp32 accum
__device__ __forceinline__ void mma8(float* d, const uint32_t* a, const uint32_t* b) {
    asm volatile(
        "mma.sync.aligned.m16n8k8.row.col.f32.tf32.tf32.f32 "
        "{%0,%1,%2,%3}, {%4,%5,%6,%7}, {%8,%9}, {%0,%1,%2,%3};\n"
        : "+f"(d[0]), "+f"(d[1]), "+f"(d[2]), "+f"(d[3])
        : "r"(a[0]), "r"(a[1]), "r"(a[2]), "r"(a[3]), "r"(b[0]), "r"(b[1]));
}

// ---------------------------------------------------------------------------
// Pre-pass: round x, w_qkv, w_proj to tf32 (rna), stored as fp32 bits.
// ---------------------------------------------------------------------------
#define N1 ((ROWS*CC)/4)
#define N2 ((CC*C3)/4)
#define N3 ((CC*CC)/4)
__global__ void cvt_pass(const float* __restrict__ x,
                         const float* __restrict__ wq,
                         const float* __restrict__ wp)
{
    int idx = blockIdx.x * 256 + threadIdx.x;
    const float4* s; float4* d;
    if (idx < N1)                { s = (const float4*)x  + idx;       d = (float4*)g_xt  + idx; }
    else if (idx < N1 + N2)      { s = (const float4*)wq + (idx-N1);  d = (float4*)g_wqt + (idx-N1); }
    else if (idx < N1 + N2 + N3) { s = (const float4*)wp + (idx-N1-N2); d = (float4*)g_wpt + (idx-N1-N2); }
    else return;
    float4 v = *s;
    v.x = __uint_as_float(f2tf32(v.x));
    v.y = __uint_as_float(f2tf32(v.y));
    v.z = __uint_as_float(f2tf32(v.z));
    v.w = __uint_as_float(f2tf32(v.w));
    *d = v;
}

// ---------------------------------------------------------------------------
// tf32 warp-MMA GEMM, cp.async double-buffered.
// C[M,Nn] = A[M,K] @ W[K,Nn] (+bias). BM=128, BN=64, BK=32. 8 warps (4x2),
// warp tile 32x32. Inputs tf32-rounded. If CVT_OUT, output tf32-rounded.
// ---------------------------------------------------------------------------
#define APAD 36                 // (4*lr+lc)&31 distinct
#define BPAD 72                 // (8*lc+lr)&31 distinct
#define AWORDS (128*APAD)       // 4608
#define BWORDS (32*BPAD)        // 2304
#define BUFW   (AWORDS+BWORDS)  // 6912
#define GEMM_SMEM_BYTES (2*BUFW*4)   // 55296

template<bool HAS_BIAS, bool CVT_OUT>
__global__ __launch_bounds__(256) void gemm_cp(const float* __restrict__ A,
                                               const float* __restrict__ W,
                                               const float* __restrict__ bias,
                                               float* __restrict__ Cm,
                                               int M, int K, int Nn)
{
    extern __shared__ uint32_t smg[];
    const uint32_t sb = smem_u32(smg);
    const int tid  = threadIdx.x;
    const int wid  = tid >> 5;
    const int lane = tid & 31;
    const int wr   = wid & 3;
    const int wc   = wid >> 2;
    const int lr   = lane >> 2;
    const int lc   = lane & 3;
    const int row0 = blockIdx.y * 128;
    const int col0 = blockIdx.x * 64;

    float acc[2][4][4];
    #pragma unroll
    for (int i = 0; i < 2; i++)
        #pragma unroll
        for (int j = 0; j < 4; j++)
            #pragma unroll
            for (int v = 0; v < 4; v++) acc[i][j][v] = 0.f;

    const int ar  = tid >> 3,  ac4 = tid & 7;    // A: 128r x 8 f4, 4 iters
    const int bk  = tid >> 4,  bc4 = tid & 15;   // B: 32r x 16 f4, 2 iters

    #define ISSUE_TILE(ch, buf) do {                                              \
        const int _k0 = (ch) * 32;                                                \
        uint32_t _ab = sb + (buf) * (BUFW * 4);                                   \
        uint32_t _bb = _ab + AWORDS * 4;                                          \
        _Pragma("unroll")                                                         \
        for (int t = 0; t < 4; t++) {                                             \
            int r = ar + t * 32;                                                  \
            cp16(_ab + (r * APAD + ac4 * 4) * 4,                                  \
                 A + (size_t)(row0 + r) * K + _k0 + ac4 * 4);                     \
        }                                                                         \
        _Pragma("unroll")                                                         \
        for (int t = 0; t < 2; t++) {                                             \
            int k = bk + t * 16;                                                  \
            cp16(_bb + (k * BPAD + bc4 * 4) * 4,                                  \
                 W + (size_t)(_k0 + k) * Nn + col0 + bc4 * 4);                    \
        }                                                                         \
    } while (0)

    const int nch = K >> 5;
    ISSUE_TILE(0, 0); cp_commit();

    for (int ch = 0; ch < nch; ch++) {
        if (ch + 1 < nch) {
            ISSUE_TILE(ch + 1, (ch + 1) & 1); cp_commit();
            cp_wait<1>();
        } else {
            cp_wait<0>();
        }
        __syncthreads();

        const uint32_t* As = smg + (ch & 1) * BUFW;
        const uint32_t* Bs = As + AWORDS;

        #pragma unroll
        for (int kk = 0; kk < 4; kk++) {
            const int ks = kk * 8;
            uint32_t af[2][4];
            #pragma unroll
            for (int mt = 0; mt < 2; mt++) {
                int r = wr * 32 + mt * 16 + lr;
                af[mt][0] = As[r * APAD + ks + lc];
                af[mt][1] = As[(r + 8) * APAD + ks + lc];
                af[mt][2] = As[r * APAD + ks + lc + 4];
                af[mt][3] = As[(r + 8) * APAD + ks + lc + 4];
            }
            #pragma unroll
            for (int nt = 0; nt < 4; nt++) {
                int n = wc * 32 + nt * 8 + lr;
                uint32_t bf[2];
                bf[0] = Bs[(ks + lc) * BPAD + n];
                bf[1] = Bs[(ks + lc + 4) * BPAD + n];
                mma8(acc[0][nt], af[0], bf);
                mma8(acc[1][nt], af[1], bf);
            }
        }
        __syncthreads();
    }
    #undef ISSUE_TILE

    #pragma unroll
    for (int mt = 0; mt < 2; mt++) {
        int r = row0 + wr * 32 + mt * 16 + lr;
        #pragma unroll
        for (int nt = 0; nt < 4; nt++) {
            int c = col0 + wc * 32 + nt * 8 + 2 * lc;
            float2 v0 = make_float2(acc[mt][nt][0], acc[mt][nt][1]);
            float2 v1 = make_float2(acc[mt][nt][2], acc[mt][nt][3]);
            if (HAS_BIAS) {
                float2 bb = *(const float2*)(bias + c);
                v0.x += bb.x; v0.y += bb.y; v1.x += bb.x; v1.y += bb.y;
            }
            if (CVT_OUT) {
                v0.x = __uint_as_float(f2tf32(v0.x));
                v0.y = __uint_as_float(f2tf32(v0.y));
                v1.x = __uint_as_float(f2tf32(v1.x));
                v1.y = __uint_as_float(f2tf32(v1.y));
            }
            *(float2*)(Cm + (size_t)r * Nn + c) = v0;
            *(float2*)(Cm + (size_t)(r + 8) * Nn + c) = v1;
        }
    }
}

// ---------------------------------------------------------------------------
// Flash attention (full 2048 keys per CTA — split-K reverted). 256 threads /
// 8 warps; each warp owns 16 query rows. Key tiles of 64, cp.async
// double-buffered. P re-fragmented via intra-quad shuffles. Q fragments from
// gmem. Output normalized + tf32-rounded, written directly to att.
// smem: buf b: K[64][68] @ b*8960w, V[64][72] @ +4352w. Total 71.7KB.
// ---------------------------------------------------------------------------
#define KP 68
#define VP 72
#define KVBUFW (64*KP + 64*VP)           // 8960
#define ATTN_SMEM_BYTES (2*KVBUFW*4)     // 71680

__global__ __launch_bounds__(256) void attn_mma(const float* __restrict__ qkv,
                                                float* __restrict__ att)
{
    extern __shared__ float sm[];
    uint32_t* smw = (uint32_t*)sm;
    const uint32_t sb = smem_u32(sm);
    const int tid  = threadIdx.x;
    const int wid  = tid >> 5;
    const int lane = tid & 31;
    const int lr   = lane >> 2;
    const int lc   = lane & 3;
    const int lc1  = lc & 1;
    const int i0   = (lane & ~3) | (lc >> 1);   // shfl src for a0/a1
    const int i2   = i0 + 2;                    // shfl src for a2/a3

    const int qt = blockIdx.x;
    const int bh = blockIdx.y;
    const int b  = bh / HH;
    const int h  = bh % HH;
    const int q0 = qt * 128;
    const float* base = qkv + (size_t)b * NN * C3;

    const int kj  = tid >> 4, kc4 = tid & 15;    // KV loads: 16 rows/iter x 16 f4
    #define ISSUE_KV(kt, buf) do {                                                \
        uint32_t _kb = sb + (buf) * (KVBUFW * 4);                                 \
        uint32_t _vb = _kb + (64 * KP) * 4;                                       \
        _Pragma("unroll")                                                         \
        for (int t = 0; t < 4; t++) {                                             \
            int j = kj + t * 16;                                                  \
            const float* row = base + (size_t)((kt) + j) * C3 + h * HD + kc4 * 4; \
            cp16(_kb + (j * KP + kc4 * 4) * 4, row + CC);                         \
            cp16(_vb + (j * VP + kc4 * 4) * 4, row + 2 * CC);                     \
        }                                                                         \
    } while (0)

    ISSUE_KV(0, 0); cp_commit();

    // Q fragments straight from gmem (rows tf32-rounded; *2^-3 exact)
    uint32_t qf[8][4];
    {
        const float scale = 0.125f;
        const float* qb = base + (size_t)(q0 + wid * 16) * C3 + h * HD;
        #pragma unroll
        for (int kk = 0; kk < 8; kk++) {
            qf[kk][0] = __float_as_uint(qb[(size_t)lr * C3 + kk * 8 + lc] * scale);
            qf[kk][1] = __float_as_uint(qb[(size_t)(lr + 8) * C3 + kk * 8 + lc] * scale);
            qf[kk][2] = __float_as_uint(qb[(size_t)lr * C3 + kk * 8 + lc + 4] * scale);
            qf[kk][3] = __float_as_uint(qb[(size_t)(lr + 8) * C3 + kk * 8 + lc + 4] * scale);
        }
    }

    float of[8][4];
    #pragma unroll
    for (int j = 0; j < 8; j++)
        #pragma unroll
        for (int v = 0; v < 4; v++) of[j][v] = 0.f;
    float m0 = -INFINITY, m1 = -INFINITY, l0 = 0.f, l1 = 0.f;

    const int ntile = NN / 64;   // 32
    for (int it = 0; it < ntile; it++) {
        if (it + 1 < ntile) {
            ISSUE_KV((it + 1) * 64, (it + 1) & 1); cp_commit();
            cp_wait<1>();
        } else {
            cp_wait<0>();
        }
        __syncthreads();

        const uint32_t* Ks = smw + (it & 1) * KVBUFW;
        const uint32_t* Vs = Ks + 64 * KP;

        // S = Q K^T
        float sf[8][4];
        #pragma unroll
        for (int nt = 0; nt < 8; nt++) {
            #pragma unroll
            for (int v = 0; v < 4; v++) sf[nt][v] = 0.f;
            #pragma unroll
            for (int kk = 0; kk < 8; kk++) {
                uint32_t bf[2];
                bf[0] = Ks[(nt * 8 + lr) * KP + kk * 8 + lc];
                bf[1] = Ks[(nt * 8 + lr) * KP + kk * 8 + lc + 4];
                mma8(sf[nt], qf[kk], bf);
            }
        }

        // online softmax
        float tm0 = -INFINITY, tm1 = -INFINITY;
        #pragma unroll
        for (int nt = 0; nt < 8; nt++) {
            tm0 = fmaxf(tm0, fmaxf(sf[nt][0], sf[nt][1]));
            tm1 = fmaxf(tm1, fmaxf(sf[nt][2], sf[nt][3]));
        }
        tm0 = fmaxf(tm0, __shfl_xor_sync(0xffffffff, tm0, 1));
        tm0 = fmaxf(tm0, __shfl_xor_sync(0xffffffff, tm0, 2));
        tm1 = fmaxf(tm1, __shfl_xor_sync(0xffffffff, tm1, 1));
        tm1 = fmaxf(tm1, __shfl_xor_sync(0xffffffff, tm1, 2));

        float mn0 = fmaxf(m0, tm0), mn1 = fmaxf(m1, tm1);
        float cr0 = __expf(m0 - mn0), cr1 = __expf(m1 - mn1);

        float rs0 = 0.f, rs1 = 0.f;
        #pragma unroll
        for (int nt = 0; nt < 8; nt++) {
            sf[nt][0] = __expf(sf[nt][0] - mn0);
            sf[nt][1] = __expf(sf[nt][1] - mn0);
            sf[nt][2] = __expf(sf[nt][2] - mn1);
            sf[nt][3] = __expf(sf[nt][3] - mn1);
            rs0 += sf[nt][0] + sf[nt][1];
            rs1 += sf[nt][2] + sf[nt][3];
        }
        rs0 += __shfl_xor_sync(0xffffffff, rs0, 1);
        rs0 += __shfl_xor_sync(0xffffffff, rs0, 2);
        rs1 += __shfl_xor_sync(0xffffffff, rs1, 1);
        rs1 += __shfl_xor_sync(0xffffffff, rs1, 2);
        l0 = l0 * cr0 + rs0;
        l1 = l1 * cr1 + rs1;
        m0 = mn0; m1 = mn1;

        #pragma unroll
        for (int dt = 0; dt < 8; dt++) {
            of[dt][0] *= cr0; of[dt][1] *= cr0;
            of[dt][2] *= cr1; of[dt][3] *= cr1;
        }

        // o += P V  — P A-fragments built via intra-quad shuffles:
        // C-frag (g,2t),(g,2t+1) -> A-frag (g,t): src lane (lane&~3)|(t>>1),
        // parity t&1; +2 lanes for cols t+4.
        #pragma unroll
        for (int kk = 0; kk < 8; kk++) {
            uint32_t pf[4];
            {
                float v00 = __shfl_sync(0xffffffff, sf[kk][0], i0);
                float v01 = __shfl_sync(0xffffffff, sf[kk][1], i0);
                pf[0] = f2tf32(lc1 ? v01 : v00);
                float v02 = __shfl_sync(0xffffffff, sf[kk][2], i0);
                float v03 = __shfl_sync(0xffffffff, sf[kk][3], i0);
                pf[1] = f2tf32(lc1 ? v03 : v02);
                float v20 = __shfl_sync(0xffffffff, sf[kk][0], i2);
                float v21 = __shfl_sync(0xffffffff, sf[kk][1], i2);
                pf[2] = f2tf32(lc1 ? v21 : v20);
                float v22 = __shfl_sync(0xffffffff, sf[kk][2], i2);
                float v23 = __shfl_sync(0xffffffff, sf[kk][3], i2);
                pf[3] = f2tf32(lc1 ? v23 : v22);
            }
            #pragma unroll
            for (int dt = 0; dt < 8; dt++) {
                uint32_t bf[2];
                bf[0] = Vs[(kk * 8 + lc) * VP + dt * 8 + lr];
                bf[1] = Vs[(kk * 8 + lc + 4) * VP + dt * 8 + lr];
                mma8(of[dt], pf, bf);
            }
        }
        __syncthreads();
    }
    #undef ISSUE_KV

    // normalize + tf32-round + write directly to att
    const float i0n = 1.f / l0, i1n = 1.f / l1;
    const int qr = q0 + wid * 16 + lr;
    #pragma unroll
    for (int dt = 0; dt < 8; dt++) {
        int c = h * HD + dt * 8 + 2 * lc;
        float2 v0, v1;
        v0.x = __uint_as_float(f2tf32(of[dt][0] * i0n));
        v0.y = __uint_as_float(f2tf32(of[dt][1] * i0n));
        v1.x = __uint_as_float(f2tf32(of[dt][2] * i1n));
        v1.y = __uint_as_float(f2tf32(of[dt][3] * i1n));
        *(float2*)(att + ((size_t)b * NN + qr) * CC + c) = v0;
        *(float2*)(att + ((size_t)b * NN + qr + 8) * CC + c) = v1;
    }
}

// ---------------------------------------------------------------------------
extern "C" void kernel_launch(void* const* d_in, const int* in_sizes, int n_in,
                              void* d_out, int out_size)
{
    const float* x      = (const float*)d_in[0];
    const float* w_qkv  = (const float*)d_in[1];
    const float* w_proj = (const float*)d_in[2];
    const float* b_proj = (const float*)d_in[3];
    float* out = (float*)d_out;

    float *qkv, *att, *xt, *wqt, *wpt;
    cudaGetSymbolAddress((void**)&qkv, g_qkv);
    cudaGetSymbolAddress((void**)&att, g_att);
    cudaGetSymbolAddress((void**)&xt,  g_xt);
    cudaGetSymbolAddress((void**)&wqt, g_wqt);
    cudaGetSymbolAddress((void**)&wpt, g_wpt);

    static bool attr_done = false;
    if (!attr_done) {
        cudaFuncSetAttribute(attn_mma, cudaFuncAttributeMaxDynamicSharedMemorySize,
                             ATTN_SMEM_BYTES);
        cudaFuncSetAttribute(gemm_cp<false, true>,
                             cudaFuncAttributeMaxDynamicSharedMemorySize, GEMM_SMEM_BYTES);
        cudaFuncSetAttribute(gemm_cp<true, false>,
                             cudaFuncAttributeMaxDynamicSharedMemorySize, GEMM_SMEM_BYTES);
        attr_done = true;
    }

    // 0) tf32 pre-round
    {
        int total = N1 + N2 + N3;
        cvt_pass<<<(total + 255) / 256, 256>>>(x, w_qkv, w_proj);
    }
    // 1) QKV projection (tf32 out)
    {
        dim3 grid(C3 / 64, ROWS / 128);
        gemm_cp<false, true><<<grid, 256, GEMM_SMEM_BYTES>>>(xt, wqt, nullptr, qkv,
                                                             ROWS, CC, C3);
    }
    // 2) attention (tf32 out, direct)
    {
        dim3 grid(QT, BB * HH);
        attn_mma<<<grid, 256, ATTN_SMEM_BYTES>>>(qkv, att);
    }
    // 3) output projection + bias (fp32 out)
    {
        dim3 grid(CC / 64, ROWS / 128);
        gemm_cp<true, false><<<grid, 256, GEMM_SMEM_BYTES>>>(att, wpt, b_proj, out,
                                                             ROWS, CC, CC);
    }
}